// round 5
// baseline (speedup 1.0000x reference)
#include <cuda_runtime.h>
#include <cuda_bf16.h>
#include <cstdint>

// Problem constants
#define Bv   2
#define Hn   16
#define Sn   4096
#define Dn   1024
#define DHn  64
#define Wn   256
#define Gn   64
#define NBn  (Sn / Wn)     // 16
#define Mtot (Bv * Sn)     // 8192
#define K3   (3 * Dn)      // 3072 (bf16-split tripled K)

// Scratch (allocation-free rule: static __device__ arrays)
__device__ float g_q[Bv * Hn * Sn * DHn];
__device__ float g_k[Bv * Hn * Sn * DHn];
__device__ float g_v[Bv * Hn * Sn * DHn];
__device__ float g_attn[Mtot * Dn];
__device__ __nv_bfloat16 g_Ae[(size_t)Mtot * K3];     // split activations
__device__ __nv_bfloat16 g_We[4][(size_t)K3 * Dn];    // split weights

// ---------------------------------------------------------------------------
// bf16-split conversion: fp32 (rows x 1024) -> [hi | lo | hi] (rows x 3072)
// ---------------------------------------------------------------------------
struct bf4 { __nv_bfloat16 v[4]; };

__global__ __launch_bounds__(256)
void conv_act_kernel(const float* __restrict__ X, __nv_bfloat16* __restrict__ Ae,
                     int total4)
{
    int i4 = blockIdx.x * 256 + threadIdx.x;
    if (i4 >= total4) return;
    int m  = i4 >> 8;             // / 256 (1024/4 chunks per row)
    int kc = (i4 & 255) * 4;
    float4 xv = *(const float4*)(X + (size_t)m * Dn + kc);
    bf4 hi, lo;
    hi.v[0] = __float2bfloat16(xv.x);
    hi.v[1] = __float2bfloat16(xv.y);
    hi.v[2] = __float2bfloat16(xv.z);
    hi.v[3] = __float2bfloat16(xv.w);
    lo.v[0] = __float2bfloat16(xv.x - __bfloat162float(hi.v[0]));
    lo.v[1] = __float2bfloat16(xv.y - __bfloat162float(hi.v[1]));
    lo.v[2] = __float2bfloat16(xv.z - __bfloat162float(hi.v[2]));
    lo.v[3] = __float2bfloat16(xv.w - __bfloat162float(hi.v[3]));
    __nv_bfloat16* row = Ae + (size_t)m * K3;
    *(bf4*)(row + kc)            = hi;  // slice 0: hi
    *(bf4*)(row + Dn + kc)       = lo;  // slice 1: lo
    *(bf4*)(row + 2 * Dn + kc)   = hi;  // slice 2: hi
}

// W (1024x1024, KxN) -> Be (3072x1024): [hi ; hi ; lo] stacked along K
__global__ __launch_bounds__(256)
void conv_w_kernel(const float* __restrict__ W, __nv_bfloat16* __restrict__ Be)
{
    int i4 = blockIdx.x * 256 + threadIdx.x;   // Dn*Dn/4 threads
    int k  = i4 >> 8;
    int nc = (i4 & 255) * 4;
    float4 wv = *(const float4*)(W + (size_t)k * Dn + nc);
    bf4 hi, lo;
    hi.v[0] = __float2bfloat16(wv.x);
    hi.v[1] = __float2bfloat16(wv.y);
    hi.v[2] = __float2bfloat16(wv.z);
    hi.v[3] = __float2bfloat16(wv.w);
    lo.v[0] = __float2bfloat16(wv.x - __bfloat162float(hi.v[0]));
    lo.v[1] = __float2bfloat16(wv.y - __bfloat162float(hi.v[1]));
    lo.v[2] = __float2bfloat16(wv.z - __bfloat162float(hi.v[2]));
    lo.v[3] = __float2bfloat16(wv.w - __bfloat162float(hi.v[3]));
    *(bf4*)(Be + (size_t)k * Dn + nc)            = hi;
    *(bf4*)(Be + (size_t)(Dn + k) * Dn + nc)     = hi;
    *(bf4*)(Be + (size_t)(2 * Dn + k) * Dn + nc) = lo;
}

// ---------------------------------------------------------------------------
// bf16 tensor-core GEMM: C(Mx1024 fp32) = Ae(Mx3072 bf16) @ Be(3072x1024 bf16)
// BM=128, BN=128, BK=32. 256 threads, 8 warps as 4(M)x2(N), warp tile 32x64.
// mma.sync.aligned.m16n8k16.row.col.f32.bf16.bf16.f32
// MODE 0: row-major C.  MODE 1: head-split write into (B,H,S,DH) layout.
// ---------------------------------------------------------------------------
__device__ __forceinline__ uint32_t smem_u32(const void* p)
{
    return (uint32_t)__cvta_generic_to_shared(p);
}

template <int MODE>
__global__ __launch_bounds__(256)
void mma_gemm_kernel(const __nv_bfloat16* __restrict__ A,
                     const __nv_bfloat16* __restrict__ B,
                     float* __restrict__ C)
{
    // padded rows for conflict-free ldmatrix (40 and 136 give distinct banks)
    __shared__ __align__(16) __nv_bfloat16 As[2][128][40];   // [m][k] 20,480 B
    __shared__ __align__(16) __nv_bfloat16 Bs[2][32][136];   // [k][n] 17,408 B

    const int tid  = threadIdx.x;
    const int bn   = blockIdx.x;   // N tile (8)
    const int bm   = blockIdx.y;   // M tile (64)
    const int warp = tid >> 5;
    const int lane = tid & 31;
    const int wm   = warp >> 1;    // 0..3
    const int wn   = warp & 1;     // 0..1

    // global loaders: A: 128 rows x 32k, thread = (row, 16-elem seg)
    const int arow = tid >> 1;
    const int aseg = (tid & 1) * 16;
    const __nv_bfloat16* Ag = A + (size_t)(bm * 128 + arow) * K3 + aseg;
    // B: 32 k-rows x 128 n, thread = (krow, 16-elem seg)
    const int brow = tid >> 3;
    const int bseg = (tid & 7) * 16;
    const __nv_bfloat16* Bg = B + (size_t)brow * Dn + bn * 128 + bseg;

    // ldmatrix per-lane address components
    const int lt = lane >> 3;      // tile 0..3
    const int lr = lane & 7;       // row in tile
    // A x4: m_off = (lt&1)*8 + lr, k_off = (lt>>1)*8
    const int a_m = wm * 32 + (lt & 1) * 8 + lr;
    const int a_k = (lt >> 1) * 8;
    // B x4.trans: k_off = (lt&1)*8 + lr, n_off = (lt>>1)*8
    const int b_k = (lt & 1) * 8 + lr;
    const int b_n = wn * 64 + (lt >> 1) * 8;

    float acc[2][8][4];
#pragma unroll
    for (int i = 0; i < 2; i++)
#pragma unroll
        for (int j = 0; j < 8; j++)
#pragma unroll
            for (int c = 0; c < 4; c++) acc[i][j][c] = 0.0f;

    uint4 ar0, ar1, br0, br1;
    // prologue: tile 0
    ar0 = *(const uint4*)(Ag);
    ar1 = *(const uint4*)(Ag + 8);
    br0 = *(const uint4*)(Bg);
    br1 = *(const uint4*)(Bg + 8);
    *(uint4*)&As[0][arow][aseg]     = ar0;
    *(uint4*)&As[0][arow][aseg + 8] = ar1;
    *(uint4*)&Bs[0][brow][bseg]     = br0;
    *(uint4*)&Bs[0][brow][bseg + 8] = br1;
    __syncthreads();

    const int NKT = K3 / 32;  // 96
    for (int kt = 0; kt < NKT; kt++) {
        const int cur = kt & 1;
        if (kt + 1 < NKT) {
            const __nv_bfloat16* Ag2 = Ag + (kt + 1) * 32;
            const __nv_bfloat16* Bg2 = Bg + (size_t)(kt + 1) * 32 * Dn;
            ar0 = *(const uint4*)(Ag2);
            ar1 = *(const uint4*)(Ag2 + 8);
            br0 = *(const uint4*)(Bg2);
            br1 = *(const uint4*)(Bg2 + 8);
        }

#pragma unroll
        for (int ks = 0; ks < 2; ks++) {
            uint32_t a[2][4];
            uint32_t b[4][4];
#pragma unroll
            for (int Mt = 0; Mt < 2; Mt++) {
                uint32_t addr = smem_u32(&As[cur][a_m + Mt * 16][ks * 16 + a_k]);
                asm volatile(
                    "ldmatrix.sync.aligned.m8n8.x4.shared.b16 {%0,%1,%2,%3}, [%4];"
                    : "=r"(a[Mt][0]), "=r"(a[Mt][1]), "=r"(a[Mt][2]), "=r"(a[Mt][3])
                    : "r"(addr));
            }
#pragma unroll
            for (int Bi = 0; Bi < 4; Bi++) {
                uint32_t addr = smem_u32(&Bs[cur][ks * 16 + b_k][b_n + Bi * 16]);
                asm volatile(
                    "ldmatrix.sync.aligned.m8n8.x4.trans.shared.b16 {%0,%1,%2,%3}, [%4];"
                    : "=r"(b[Bi][0]), "=r"(b[Bi][1]), "=r"(b[Bi][2]), "=r"(b[Bi][3])
                    : "r"(addr));
            }
#pragma unroll
            for (int Mt = 0; Mt < 2; Mt++) {
#pragma unroll
                for (int no = 0; no < 8; no++) {
                    const uint32_t b0 = b[no >> 1][(no & 1) * 2];
                    const uint32_t b1 = b[no >> 1][(no & 1) * 2 + 1];
                    asm volatile(
                        "mma.sync.aligned.m16n8k16.row.col.f32.bf16.bf16.f32 "
                        "{%0,%1,%2,%3}, {%4,%5,%6,%7}, {%8,%9}, {%0,%1,%2,%3};"
                        : "+f"(acc[Mt][no][0]), "+f"(acc[Mt][no][1]),
                          "+f"(acc[Mt][no][2]), "+f"(acc[Mt][no][3])
                        : "r"(a[Mt][0]), "r"(a[Mt][1]), "r"(a[Mt][2]), "r"(a[Mt][3]),
                          "r"(b0), "r"(b1));
                }
            }
        }

        if (kt + 1 < NKT) {
            const int nxt = cur ^ 1;
            *(uint4*)&As[nxt][arow][aseg]     = ar0;
            *(uint4*)&As[nxt][arow][aseg + 8] = ar1;
            *(uint4*)&Bs[nxt][brow][bseg]     = br0;
            *(uint4*)&Bs[nxt][brow][bseg + 8] = br1;
            __syncthreads();
        }
    }

    // epilogue
    const int g  = lane >> 2;
    const int tq = lane & 3;
#pragma unroll
    for (int Mt = 0; Mt < 2; Mt++) {
#pragma unroll
        for (int no = 0; no < 8; no++) {
            const int row = bm * 128 + wm * 32 + Mt * 16 + g;
            const int col = bn * 128 + wn * 64 + no * 8 + tq * 2;
            if (MODE == 0) {
                float2 t0 = make_float2(acc[Mt][no][0], acc[Mt][no][1]);
                float2 t1 = make_float2(acc[Mt][no][2], acc[Mt][no][3]);
                *(float2*)(C + (size_t)row * Dn + col)       = t0;
                *(float2*)(C + (size_t)(row + 8) * Dn + col) = t1;
            } else {
                const int h  = col >> 6;
                const int dh = col & 63;
#pragma unroll
                for (int rr = 0; rr < 2; rr++) {
                    const int r = row + rr * 8;
                    const int b = r >> 12;
                    const int s = r & 4095;
                    float2 t = make_float2(acc[Mt][no][rr * 2],
                                           acc[Mt][no][rr * 2 + 1]);
                    *(float2*)(g_q + 0) ;  // (no-op placeholder removed below)
                    float* dst = C + (((size_t)(b * Hn + h) * Sn) + s) * DHn + dh;
                    *(float2*)dst = t;
                }
            }
        }
    }
}

// ---------------------------------------------------------------------------
// Attention: one CTA per (block n, head h, batch b). 256 threads, one query
// per thread. fp32 throughout (accuracy anchor). float4 smem reads.
// ---------------------------------------------------------------------------
__global__ __launch_bounds__(256, 1)
void attn_kernel(const float* __restrict__ q, const float* __restrict__ k,
                 const float* __restrict__ v, float* __restrict__ out)
{
    __shared__ float Ks[64][64];
    __shared__ float Vs[64][64];

    const int n = blockIdx.x, h = blockIdx.y, b = blockIdx.z;
    const int tid = threadIdx.x;
    const int i_abs = n * Wn + tid;

    const float* basek = k + (size_t)((b * Hn + h) * Sn) * DHn;
    const float* basev = v + (size_t)((b * Hn + h) * Sn) * DHn;

    float qr[64];
    {
        const float scale = 0.125f;
        const float* qp = q + ((size_t)(b * Hn + h) * Sn + i_abs) * DHn;
#pragma unroll
        for (int d = 0; d < 64; d += 4) {
            float4 t = *(const float4*)(qp + d);
            qr[d] = t.x * scale; qr[d + 1] = t.y * scale;
            qr[d + 2] = t.z * scale; qr[d + 3] = t.w * scale;
        }
    }

    float accv[64];
#pragma unroll
    for (int d = 0; d < 64; d++) accv[d] = 0.0f;
    float lsum = 0.0f;

    const int jrow = tid >> 2;
    const int dcol = (tid & 3) * 16;
    const int wq0 = n * Wn + (tid & ~31);

    const int jlo = (n * Wn - Wn > Gn) ? (n * Wn - Wn) : Gn;
    const int jhi = (n * Wn + 2 * Wn < Sn) ? (n * Wn + 2 * Wn) : Sn;
    const int nloc = (jhi - jlo) >> 6;

    for (int c = -1; c < nloc; c++) {
        const int jb = (c < 0) ? 0 : (jlo + (c << 6));
        const bool is_global = (c < 0);

        {
            const float* ksrc = basek + (size_t)(jb + jrow) * DHn + dcol;
            const float* vsrc = basev + (size_t)(jb + jrow) * DHn + dcol;
#pragma unroll
            for (int u = 0; u < 16; u += 4) {
                *(float4*)&Ks[jrow][dcol + u] = *(const float4*)(ksrc + u);
                *(float4*)&Vs[jrow][dcol + u] = *(const float4*)(vsrc + u);
            }
        }
        __syncthreads();

        bool warp_live = is_global ||
                         ((jb + 63 >= wq0 - Wn) && (jb <= wq0 + 31 + Wn));
        if (warp_live) {
            for (int j = 0; j < 64; j++) {
                const int ja = jb + j;
                const bool valid =
                    is_global || ((ja >= i_abs - Wn) && (ja <= i_abs + Wn));
                const float4* k4 = (const float4*)&Ks[j][0];
                float s0 = 0.f, s1 = 0.f, s2 = 0.f, s3 = 0.f;
#pragma unroll
                for (int d4 = 0; d4 < 16; d4++) {
                    float4 kk = k4[d4];
                    s0 += qr[d4 * 4 + 0] * kk.x;
                    s1 += qr[d4 * 4 + 1] * kk.y;
                    s2 += qr[d4 * 4 + 2] * kk.z;
                    s3 += qr[d4 * 4 + 3] * kk.w;
                }
                const float s = (s0 + s1) + (s2 + s3);
                const float p = valid ? __expf(s) : 0.0f;
                lsum += p;
                const float4* v4 = (const float4*)&Vs[j][0];
#pragma unroll
                for (int d4 = 0; d4 < 16; d4++) {
                    float4 vv = v4[d4];
                    accv[d4 * 4 + 0] += p * vv.x;
                    accv[d4 * 4 + 1] += p * vv.y;
                    accv[d4 * 4 + 2] += p * vv.z;
                    accv[d4 * 4 + 3] += p * vv.w;
                }
            }
        }
        __syncthreads();
    }

    const float inv = 1.0f / lsum;
    float* op = out + ((size_t)(b * Sn + i_abs)) * Dn + h * DHn;
#pragma unroll
    for (int d = 0; d < 64; d += 4) {
        float4 t;
        t.x = accv[d] * inv;     t.y = accv[d + 1] * inv;
        t.z = accv[d + 2] * inv; t.w = accv[d + 3] * inv;
        *(float4*)(op + d) = t;
    }
}

// ---------------------------------------------------------------------------
// kernel_launch — inputs: x, Wq, Wk, Wv, Wo (all float32)
// ---------------------------------------------------------------------------
extern "C" void kernel_launch(void* const* d_in, const int* in_sizes, int n_in,
                              void* d_out, int out_size)
{
    (void)in_sizes; (void)n_in; (void)out_size;
    const float* x  = (const float*)d_in[0];
    const float* Wq = (const float*)d_in[1];
    const float* Wk = (const float*)d_in[2];
    const float* Wv = (const float*)d_in[3];
    const float* Wo = (const float*)d_in[4];
    float* out = (float*)d_out;

    void *pq, *pk, *pv, *pa, *pae, *pwe;
    cudaGetSymbolAddress(&pq, g_q);
    cudaGetSymbolAddress(&pk, g_k);
    cudaGetSymbolAddress(&pv, g_v);
    cudaGetSymbolAddress(&pa, g_attn);
    cudaGetSymbolAddress(&pae, g_Ae);
    cudaGetSymbolAddress(&pwe, g_We);
    float* q    = (float*)pq;
    float* k    = (float*)pk;
    float* v    = (float*)pv;
    float* attn = (float*)pa;
    __nv_bfloat16* Ae = (__nv_bfloat16*)pae;
    __nv_bfloat16* We = (__nv_bfloat16*)pwe;
    const size_t wstride = (size_t)K3 * Dn;

    // split conversions
    const int act4 = Mtot * Dn / 4;          // 2,097,152
    const int w4   = Dn * Dn / 4;            // 262,144
    conv_w_kernel<<<w4 / 256, 256>>>(Wq, We + 0 * wstride);
    conv_w_kernel<<<w4 / 256, 256>>>(Wk, We + 1 * wstride);
    conv_w_kernel<<<w4 / 256, 256>>>(Wv, We + 2 * wstride);
    conv_w_kernel<<<w4 / 256, 256>>>(Wo, We + 3 * wstride);
    conv_act_kernel<<<act4 / 256, 256>>>(x, Ae, act4);

    dim3 gemm_grid(Dn / 128, Mtot / 128);  // (8, 64)
    mma_gemm_kernel<1><<<gemm_grid, 256>>>(Ae, We + 0 * wstride, q);
    mma_gemm_kernel<1><<<gemm_grid, 256>>>(Ae, We + 1 * wstride, k);
    mma_gemm_kernel<1><<<gemm_grid, 256>>>(Ae, We + 2 * wstride, v);

    dim3 attn_grid(NBn, Hn, Bv);  // (16, 16, 2)
    attn_kernel<<<attn_grid, 256>>>(q, k, v, attn);

    conv_act_kernel<<<act4 / 256, 256>>>(attn, Ae, act4);
    mma_gemm_kernel<0><<<gemm_grid, 256>>>(Ae, We + 3 * wstride, out);
}

// round 6
// speedup vs baseline: 1.0016x; 1.0016x over previous
#include <cuda_runtime.h>
#include <cuda_bf16.h>
#include <cstdint>

// Problem constants
#define Bv   2
#define Hn   16
#define Sn   4096
#define Dn   1024
#define DHn  64
#define Wn   256
#define Gn   64
#define NBn  (Sn / Wn)     // 16
#define Mtot (Bv * Sn)     // 8192
#define K3   (3 * Dn)      // 3072 (bf16-split tripled K)

// Scratch (allocation-free rule: static __device__ arrays)
__device__ float g_q[Bv * Hn * Sn * DHn];
__device__ float g_k[Bv * Hn * Sn * DHn];
__device__ float g_v[Bv * Hn * Sn * DHn];
__device__ float g_attn[Mtot * Dn];
__device__ __nv_bfloat16 g_Ae[(size_t)Mtot * K3];     // split activations
__device__ __nv_bfloat16 g_We[4][(size_t)K3 * Dn];    // split weights

// ---------------------------------------------------------------------------
// bf16-split conversion: fp32 (rows x 1024) -> [hi | lo | hi] (rows x 3072)
// ---------------------------------------------------------------------------
struct bf4 { __nv_bfloat16 v[4]; };

__global__ __launch_bounds__(256)
void conv_act_kernel(const float* __restrict__ X, __nv_bfloat16* __restrict__ Ae,
                     int total4)
{
    int i4 = blockIdx.x * 256 + threadIdx.x;
    if (i4 >= total4) return;
    int m  = i4 >> 8;             // / 256 (1024/4 chunks per row)
    int kc = (i4 & 255) * 4;
    float4 xv = *(const float4*)(X + (size_t)m * Dn + kc);
    bf4 hi, lo;
    hi.v[0] = __float2bfloat16(xv.x);
    hi.v[1] = __float2bfloat16(xv.y);
    hi.v[2] = __float2bfloat16(xv.z);
    hi.v[3] = __float2bfloat16(xv.w);
    lo.v[0] = __float2bfloat16(xv.x - __bfloat162float(hi.v[0]));
    lo.v[1] = __float2bfloat16(xv.y - __bfloat162float(hi.v[1]));
    lo.v[2] = __float2bfloat16(xv.z - __bfloat162float(hi.v[2]));
    lo.v[3] = __float2bfloat16(xv.w - __bfloat162float(hi.v[3]));
    __nv_bfloat16* row = Ae + (size_t)m * K3;
    *(bf4*)(row + kc)            = hi;  // slice 0: hi
    *(bf4*)(row + Dn + kc)       = lo;  // slice 1: lo
    *(bf4*)(row + 2 * Dn + kc)   = hi;  // slice 2: hi
}

// W (1024x1024, KxN) -> Be (3072x1024): [hi ; hi ; lo] stacked along K
__global__ __launch_bounds__(256)
void conv_w_kernel(const float* __restrict__ W, __nv_bfloat16* __restrict__ Be)
{
    int i4 = blockIdx.x * 256 + threadIdx.x;   // Dn*Dn/4 threads
    int k  = i4 >> 8;
    int nc = (i4 & 255) * 4;
    float4 wv = *(const float4*)(W + (size_t)k * Dn + nc);
    bf4 hi, lo;
    hi.v[0] = __float2bfloat16(wv.x);
    hi.v[1] = __float2bfloat16(wv.y);
    hi.v[2] = __float2bfloat16(wv.z);
    hi.v[3] = __float2bfloat16(wv.w);
    lo.v[0] = __float2bfloat16(wv.x - __bfloat162float(hi.v[0]));
    lo.v[1] = __float2bfloat16(wv.y - __bfloat162float(hi.v[1]));
    lo.v[2] = __float2bfloat16(wv.z - __bfloat162float(hi.v[2]));
    lo.v[3] = __float2bfloat16(wv.w - __bfloat162float(hi.v[3]));
    *(bf4*)(Be + (size_t)k * Dn + nc)            = hi;
    *(bf4*)(Be + (size_t)(Dn + k) * Dn + nc)     = hi;
    *(bf4*)(Be + (size_t)(2 * Dn + k) * Dn + nc) = lo;
}

// ---------------------------------------------------------------------------
// bf16 tensor-core GEMM: C(Mx1024 fp32) = Ae(Mx3072 bf16) @ Be(3072x1024 bf16)
// BM=128, BN=128, BK=32. 256 threads, 8 warps as 4(M)x2(N), warp tile 32x64.
// mma.sync.aligned.m16n8k16.row.col.f32.bf16.bf16.f32
// MODE 0: row-major C.  MODE 1: head-split write into (B,H,S,DH) layout.
// ---------------------------------------------------------------------------
__device__ __forceinline__ uint32_t smem_u32(const void* p)
{
    return (uint32_t)__cvta_generic_to_shared(p);
}

template <int MODE>
__global__ __launch_bounds__(256)
void mma_gemm_kernel(const __nv_bfloat16* __restrict__ A,
                     const __nv_bfloat16* __restrict__ B,
                     float* __restrict__ C)
{
    // padded rows for conflict-free ldmatrix (40 and 136 give distinct banks)
    __shared__ __align__(16) __nv_bfloat16 As[2][128][40];   // [m][k] 20,480 B
    __shared__ __align__(16) __nv_bfloat16 Bs[2][32][136];   // [k][n] 17,408 B

    const int tid  = threadIdx.x;
    const int bn   = blockIdx.x;   // N tile (8)
    const int bm   = blockIdx.y;   // M tile (64)
    const int warp = tid >> 5;
    const int lane = tid & 31;
    const int wm   = warp >> 1;    // 0..3
    const int wn   = warp & 1;     // 0..1

    // global loaders: A: 128 rows x 32k, thread = (row, 16-elem seg)
    const int arow = tid >> 1;
    const int aseg = (tid & 1) * 16;
    const __nv_bfloat16* Ag = A + (size_t)(bm * 128 + arow) * K3 + aseg;
    // B: 32 k-rows x 128 n, thread = (krow, 16-elem seg)
    const int brow = tid >> 3;
    const int bseg = (tid & 7) * 16;
    const __nv_bfloat16* Bg = B + (size_t)brow * Dn + bn * 128 + bseg;

    // ldmatrix per-lane address components
    const int lt = lane >> 3;      // tile 0..3
    const int lr = lane & 7;       // row in tile
    // A x4: m_off = (lt&1)*8 + lr, k_off = (lt>>1)*8
    const int a_m = wm * 32 + (lt & 1) * 8 + lr;
    const int a_k = (lt >> 1) * 8;
    // B x4.trans: k_off = (lt&1)*8 + lr, n_off = (lt>>1)*8
    const int b_k = (lt & 1) * 8 + lr;
    const int b_n = wn * 64 + (lt >> 1) * 8;

    float acc[2][8][4];
#pragma unroll
    for (int i = 0; i < 2; i++)
#pragma unroll
        for (int j = 0; j < 8; j++)
#pragma unroll
            for (int c = 0; c < 4; c++) acc[i][j][c] = 0.0f;

    uint4 ar0, ar1, br0, br1;
    // prologue: tile 0
    ar0 = *(const uint4*)(Ag);
    ar1 = *(const uint4*)(Ag + 8);
    br0 = *(const uint4*)(Bg);
    br1 = *(const uint4*)(Bg + 8);
    *(uint4*)&As[0][arow][aseg]     = ar0;
    *(uint4*)&As[0][arow][aseg + 8] = ar1;
    *(uint4*)&Bs[0][brow][bseg]     = br0;
    *(uint4*)&Bs[0][brow][bseg + 8] = br1;
    __syncthreads();

    const int NKT = K3 / 32;  // 96
    for (int kt = 0; kt < NKT; kt++) {
        const int cur = kt & 1;
        if (kt + 1 < NKT) {
            const __nv_bfloat16* Ag2 = Ag + (kt + 1) * 32;
            const __nv_bfloat16* Bg2 = Bg + (size_t)(kt + 1) * 32 * Dn;
            ar0 = *(const uint4*)(Ag2);
            ar1 = *(const uint4*)(Ag2 + 8);
            br0 = *(const uint4*)(Bg2);
            br1 = *(const uint4*)(Bg2 + 8);
        }

#pragma unroll
        for (int ks = 0; ks < 2; ks++) {
            uint32_t a[2][4];
            uint32_t b[4][4];
#pragma unroll
            for (int Mt = 0; Mt < 2; Mt++) {
                uint32_t addr = smem_u32(&As[cur][a_m + Mt * 16][ks * 16 + a_k]);
                asm volatile(
                    "ldmatrix.sync.aligned.m8n8.x4.shared.b16 {%0,%1,%2,%3}, [%4];"
                    : "=r"(a[Mt][0]), "=r"(a[Mt][1]), "=r"(a[Mt][2]), "=r"(a[Mt][3])
                    : "r"(addr));
            }
#pragma unroll
            for (int Bi = 0; Bi < 4; Bi++) {
                uint32_t addr = smem_u32(&Bs[cur][ks * 16 + b_k][b_n + Bi * 16]);
                asm volatile(
                    "ldmatrix.sync.aligned.m8n8.x4.trans.shared.b16 {%0,%1,%2,%3}, [%4];"
                    : "=r"(b[Bi][0]), "=r"(b[Bi][1]), "=r"(b[Bi][2]), "=r"(b[Bi][3])
                    : "r"(addr));
            }
#pragma unroll
            for (int Mt = 0; Mt < 2; Mt++) {
#pragma unroll
                for (int no = 0; no < 8; no++) {
                    const uint32_t b0 = b[no >> 1][(no & 1) * 2];
                    const uint32_t b1 = b[no >> 1][(no & 1) * 2 + 1];
                    asm volatile(
                        "mma.sync.aligned.m16n8k16.row.col.f32.bf16.bf16.f32 "
                        "{%0,%1,%2,%3}, {%4,%5,%6,%7}, {%8,%9}, {%0,%1,%2,%3};"
                        : "+f"(acc[Mt][no][0]), "+f"(acc[Mt][no][1]),
                          "+f"(acc[Mt][no][2]), "+f"(acc[Mt][no][3])
                        : "r"(a[Mt][0]), "r"(a[Mt][1]), "r"(a[Mt][2]), "r"(a[Mt][3]),
                          "r"(b0), "r"(b1));
                }
            }
        }

        if (kt + 1 < NKT) {
            const int nxt = cur ^ 1;
            *(uint4*)&As[nxt][arow][aseg]     = ar0;
            *(uint4*)&As[nxt][arow][aseg + 8] = ar1;
            *(uint4*)&Bs[nxt][brow][bseg]     = br0;
            *(uint4*)&Bs[nxt][brow][bseg + 8] = br1;
            __syncthreads();
        }
    }

    // epilogue
    const int g  = lane >> 2;
    const int tq = lane & 3;
#pragma unroll
    for (int Mt = 0; Mt < 2; Mt++) {
#pragma unroll
        for (int no = 0; no < 8; no++) {
            const int row = bm * 128 + wm * 32 + Mt * 16 + g;
            const int col = bn * 128 + wn * 64 + no * 8 + tq * 2;
            if (MODE == 0) {
                float2 t0 = make_float2(acc[Mt][no][0], acc[Mt][no][1]);
                float2 t1 = make_float2(acc[Mt][no][2], acc[Mt][no][3]);
                *(float2*)(C + (size_t)row * Dn + col)       = t0;
                *(float2*)(C + (size_t)(row + 8) * Dn + col) = t1;
            } else {
                const int h  = col >> 6;
                const int dh = col & 63;
#pragma unroll
                for (int rr = 0; rr < 2; rr++) {
                    const int r = row + rr * 8;
                    const int b = r >> 12;
                    const int s = r & 4095;
                    float2 t = make_float2(acc[Mt][no][rr * 2],
                                           acc[Mt][no][rr * 2 + 1]);
                    *(float2*)(g_q + 0) ;  // (no-op placeholder removed below)
                    float* dst = C + (((size_t)(b * Hn + h) * Sn) + s) * DHn + dh;
                    *(float2*)dst = t;
                }
            }
        }
    }
}

// ---------------------------------------------------------------------------
// Attention: one CTA per (block n, head h, batch b). 256 threads, one query
// per thread. fp32 throughout (accuracy anchor). float4 smem reads.
// ---------------------------------------------------------------------------
__global__ __launch_bounds__(256, 1)
void attn_kernel(const float* __restrict__ q, const float* __restrict__ k,
                 const float* __restrict__ v, float* __restrict__ out)
{
    __shared__ float Ks[64][64];
    __shared__ float Vs[64][64];

    const int n = blockIdx.x, h = blockIdx.y, b = blockIdx.z;
    const int tid = threadIdx.x;
    const int i_abs = n * Wn + tid;

    const float* basek = k + (size_t)((b * Hn + h) * Sn) * DHn;
    const float* basev = v + (size_t)((b * Hn + h) * Sn) * DHn;

    float qr[64];
    {
        const float scale = 0.125f;
        const float* qp = q + ((size_t)(b * Hn + h) * Sn + i_abs) * DHn;
#pragma unroll
        for (int d = 0; d < 64; d += 4) {
            float4 t = *(const float4*)(qp + d);
            qr[d] = t.x * scale; qr[d + 1] = t.y * scale;
            qr[d + 2] = t.z * scale; qr[d + 3] = t.w * scale;
        }
    }

    float accv[64];
#pragma unroll
    for (int d = 0; d < 64; d++) accv[d] = 0.0f;
    float lsum = 0.0f;

    const int jrow = tid >> 2;
    const int dcol = (tid & 3) * 16;
    const int wq0 = n * Wn + (tid & ~31);

    const int jlo = (n * Wn - Wn > Gn) ? (n * Wn - Wn) : Gn;
    const int jhi = (n * Wn + 2 * Wn < Sn) ? (n * Wn + 2 * Wn) : Sn;
    const int nloc = (jhi - jlo) >> 6;

    for (int c = -1; c < nloc; c++) {
        const int jb = (c < 0) ? 0 : (jlo + (c << 6));
        const bool is_global = (c < 0);

        {
            const float* ksrc = basek + (size_t)(jb + jrow) * DHn + dcol;
            const float* vsrc = basev + (size_t)(jb + jrow) * DHn + dcol;
#pragma unroll
            for (int u = 0; u < 16; u += 4) {
                *(float4*)&Ks[jrow][dcol + u] = *(const float4*)(ksrc + u);
                *(float4*)&Vs[jrow][dcol + u] = *(const float4*)(vsrc + u);
            }
        }
        __syncthreads();

        bool warp_live = is_global ||
                         ((jb + 63 >= wq0 - Wn) && (jb <= wq0 + 31 + Wn));
        if (warp_live) {
            for (int j = 0; j < 64; j++) {
                const int ja = jb + j;
                const bool valid =
                    is_global || ((ja >= i_abs - Wn) && (ja <= i_abs + Wn));
                const float4* k4 = (const float4*)&Ks[j][0];
                float s0 = 0.f, s1 = 0.f, s2 = 0.f, s3 = 0.f;
#pragma unroll
                for (int d4 = 0; d4 < 16; d4++) {
                    float4 kk = k4[d4];
                    s0 += qr[d4 * 4 + 0] * kk.x;
                    s1 += qr[d4 * 4 + 1] * kk.y;
                    s2 += qr[d4 * 4 + 2] * kk.z;
                    s3 += qr[d4 * 4 + 3] * kk.w;
                }
                const float s = (s0 + s1) + (s2 + s3);
                const float p = valid ? __expf(s) : 0.0f;
                lsum += p;
                const float4* v4 = (const float4*)&Vs[j][0];
#pragma unroll
                for (int d4 = 0; d4 < 16; d4++) {
                    float4 vv = v4[d4];
                    accv[d4 * 4 + 0] += p * vv.x;
                    accv[d4 * 4 + 1] += p * vv.y;
                    accv[d4 * 4 + 2] += p * vv.z;
                    accv[d4 * 4 + 3] += p * vv.w;
                }
            }
        }
        __syncthreads();
    }

    const float inv = 1.0f / lsum;
    float* op = out + ((size_t)(b * Sn + i_abs)) * Dn + h * DHn;
#pragma unroll
    for (int d = 0; d < 64; d += 4) {
        float4 t;
        t.x = accv[d] * inv;     t.y = accv[d + 1] * inv;
        t.z = accv[d + 2] * inv; t.w = accv[d + 3] * inv;
        *(float4*)(op + d) = t;
    }
}

// ---------------------------------------------------------------------------
// kernel_launch — inputs: x, Wq, Wk, Wv, Wo (all float32)
// ---------------------------------------------------------------------------
extern "C" void kernel_launch(void* const* d_in, const int* in_sizes, int n_in,
                              void* d_out, int out_size)
{
    (void)in_sizes; (void)n_in; (void)out_size;
    const float* x  = (const float*)d_in[0];
    const float* Wq = (const float*)d_in[1];
    const float* Wk = (const float*)d_in[2];
    const float* Wv = (const float*)d_in[3];
    const float* Wo = (const float*)d_in[4];
    float* out = (float*)d_out;

    void *pq, *pk, *pv, *pa, *pae, *pwe;
    cudaGetSymbolAddress(&pq, g_q);
    cudaGetSymbolAddress(&pk, g_k);
    cudaGetSymbolAddress(&pv, g_v);
    cudaGetSymbolAddress(&pa, g_attn);
    cudaGetSymbolAddress(&pae, g_Ae);
    cudaGetSymbolAddress(&pwe, g_We);
    float* q    = (float*)pq;
    float* k    = (float*)pk;
    float* v    = (float*)pv;
    float* attn = (float*)pa;
    __nv_bfloat16* Ae = (__nv_bfloat16*)pae;
    __nv_bfloat16* We = (__nv_bfloat16*)pwe;
    const size_t wstride = (size_t)K3 * Dn;

    // split conversions
    const int act4 = Mtot * Dn / 4;          // 2,097,152
    const int w4   = Dn * Dn / 4;            // 262,144
    conv_w_kernel<<<w4 / 256, 256>>>(Wq, We + 0 * wstride);
    conv_w_kernel<<<w4 / 256, 256>>>(Wk, We + 1 * wstride);
    conv_w_kernel<<<w4 / 256, 256>>>(Wv, We + 2 * wstride);
    conv_w_kernel<<<w4 / 256, 256>>>(Wo, We + 3 * wstride);
    conv_act_kernel<<<act4 / 256, 256>>>(x, Ae, act4);

    dim3 gemm_grid(Dn / 128, Mtot / 128);  // (8, 64)
    mma_gemm_kernel<1><<<gemm_grid, 256>>>(Ae, We + 0 * wstride, q);
    mma_gemm_kernel<1><<<gemm_grid, 256>>>(Ae, We + 1 * wstride, k);
    mma_gemm_kernel<1><<<gemm_grid, 256>>>(Ae, We + 2 * wstride, v);

    dim3 attn_grid(NBn, Hn, Bv);  // (16, 16, 2)
    attn_kernel<<<attn_grid, 256>>>(q, k, v, attn);

    conv_act_kernel<<<act4 / 256, 256>>>(attn, Ae, act4);
    mma_gemm_kernel<0><<<gemm_grid, 256>>>(Ae, We + 3 * wstride, out);
}